// round 5
// baseline (speedup 1.0000x reference)
#include <cuda_runtime.h>
#include <cstdint>

// ============================================================================
// BLinear: out[t][o] = sum_i sign(x[t,i])*sign(W[o,i]) + b[o]
// sm_100 (no tcgen05). s8 +-1 IMMA GEMM with cp.async.bulk stage loads from a
// pre-swizzled gmem layout (pack kernels emit the exact smem stage images).
// ============================================================================

#define TPB 512
#define TM 128
#define TN 256
#define TKB 64                      // K bytes per stage
#define STAGES 6

#define A_BLK (TM * TKB)            // 8192
#define B_BLK (TN * TKB)            // 16384
#define STAGE_BYTES (A_BLK + B_BLK) // 24576
#define SMEM_CTRL 1024
#define SMEM_TOTAL (SMEM_CTRL + STAGES * STAGE_BYTES)   // 148480

#define OFF_FULL  0                 // 6 x 8B mbarriers
#define OFF_EMPTY 64                // 6 x 8B mbarriers

// Scratch (__device__ globals per allocation rules)
__device__ __align__(256) int8_t g_Xa[8192u * 2048u];   // 16 MB, [T/128][K/64][8192]
__device__ __align__(256) int8_t g_Wb[2048u * 2048u];   //  4 MB, [O/256][K/64][16384]

__device__ __forceinline__ uint32_t smem_u32(const void* p) {
    uint32_t a;
    asm("{ .reg .u64 t; cvta.to.shared.u64 t, %1; cvt.u32.u64 %0, t; }"
        : "=r"(a) : "l"(p));
    return a;
}
#define MBARRIER_INIT(addr, count) \
    asm volatile("mbarrier.init.shared.b64 [%0], %1;" \
        :: "r"((uint32_t)(addr)), "r"((uint32_t)(count)) : "memory")
#define MBARRIER_ARRIVE(addr) \
    asm volatile("mbarrier.arrive.release.cta.shared.b64 _, [%0];" \
        :: "r"((uint32_t)(addr)) : "memory")
#define MBARRIER_EXPECT_TX(addr, tx) \
    asm volatile("mbarrier.arrive.expect_tx.shared.b64 _, [%0], %1;" \
        :: "r"((uint32_t)(addr)), "r"((uint32_t)(tx)) : "memory")
#define MBARRIER_WAIT_PARITY(addr, parity) do { \
    uint32_t _m = (uint32_t)(addr); \
    uint32_t _p = (uint32_t)(parity); \
    uint32_t _done; \
    asm volatile("{\n\t.reg .pred p;\n\t" \
        "mbarrier.try_wait.parity.acquire.cta.shared::cta.b64 p, [%1], %2;\n\t" \
        "selp.b32 %0, 1, 0, p;\n\t}" \
        : "=r"(_done) : "r"(_m), "r"(_p) : "memory"); \
    if (!_done) { \
        asm volatile("{\n\t.reg .pred P1;\n\t" \
            "WL_%=:\n\t" \
            "mbarrier.try_wait.parity.acquire.cta.shared::cta.b64 P1, [%0], %1, 0x989680;\n\t" \
            "@P1 bra.uni WD_%=;\n\t" \
            "bra.uni WL_%=;\n\t" \
            "WD_%=:\n\t}" \
            :: "r"(_m), "r"(_p) : "memory"); \
    } \
} while (0)

__device__ __forceinline__ void bulk_cp(uint32_t dst, const void* src,
                                        uint32_t bytes, uint32_t mbar) {
    asm volatile(
        "cp.async.bulk.shared::cluster.global.mbarrier::complete_tx::bytes "
        "[%0], [%1], %2, [%3];"
        :: "r"(dst), "l"(src), "r"(bytes), "r"(mbar) : "memory");
}
__device__ __forceinline__ void ldm_x4(uint32_t& r0, uint32_t& r1,
                                       uint32_t& r2, uint32_t& r3, uint32_t addr) {
    asm volatile("ldmatrix.sync.aligned.m8n8.x4.shared.b16 {%0,%1,%2,%3}, [%4];"
        : "=r"(r0), "=r"(r1), "=r"(r2), "=r"(r3) : "r"(addr));
}
__device__ __forceinline__ void imma(int* d, const uint32_t* a, const uint32_t* b) {
    asm volatile("mma.sync.aligned.m16n8k32.row.col.s32.s8.s8.s32 "
        "{%0,%1,%2,%3}, {%4,%5,%6,%7}, {%8,%9}, {%0,%1,%2,%3};"
        : "+r"(d[0]), "+r"(d[1]), "+r"(d[2]), "+r"(d[3])
        : "r"(a[0]), "r"(a[1]), "r"(a[2]), "r"(a[3]), "r"(b[0]), "r"(b[1]));
}

// 16B-chunk XOR swizzle within a 64B k-row (row stride 64B).
__device__ __forceinline__ uint32_t swz(int r, int c) {
    return (uint32_t)(r * TKB + ((c ^ ((r >> 1) & 3)) << 4));
}

// ---------------------------------------------------------------------------
// Pack fp32 -> s8 sign into pre-swizzled tile-chunk blocks.
// Thread i handles 16 consecutive k of one row: 16B chunk (r, kc16).
// rows_per_blk = TM (A) or TN (B); blk_bytes = rows_per_blk * 64.
// ---------------------------------------------------------------------------
template<int ROWS_PER_BLK>
__global__ void __launch_bounds__(256)
pack_s8_tiled(const float* __restrict__ src, int8_t* __restrict__ dst,
              int n16, int KW16 /* K/16 */, int kchunks /* K/64 */)
{
    int idx = blockIdx.x * blockDim.x + threadIdx.x;
    int stride = gridDim.x * blockDim.x;
    const int blk_bytes = ROWS_PER_BLK * TKB;
    for (int i = idx; i < n16; i += stride) {
        int r    = i / KW16;
        int kc16 = i - r * KW16;
        int kc   = kc16 >> 2;
        int c    = kc16 & 3;
        int rb   = r / ROWS_PER_BLK;
        int rr   = r - rb * ROWS_PER_BLK;

        const float4* s4 = (const float4*)(src + (size_t)r * (KW16 * 16) + kc16 * 16);
        uint32_t w[4];
#pragma unroll
        for (int k = 0; k < 4; k++) {
            float4 f = s4[k];
            uint32_t sb = (__float_as_uint(f.x) >> 31)
                        | ((__float_as_uint(f.y) >> 31) << 8)
                        | ((__float_as_uint(f.z) >> 31) << 16)
                        | ((__float_as_uint(f.w) >> 31) << 24);
            w[k] = 0x01010101u ^ (sb * 0xFEu);   // +1 -> 0x01, -1 -> 0xFF
        }
        size_t doff = ((size_t)rb * kchunks + kc) * blk_bytes + swz(rr, c);
        *(uint4*)(dst + doff) = make_uint4(w[0], w[1], w[2], w[3]);
    }
}

// ---------------------------------------------------------------------------
// IMMA GEMM, 128x256 tile, 16 warps (warp tile 32x64), bulk-copy pipeline.
// ---------------------------------------------------------------------------
__global__ void __launch_bounds__(TPB, 1)
bgemm_imma(const int8_t* __restrict__ A, const int8_t* __restrict__ B,
           const float* __restrict__ bias, float* __restrict__ out,
           int T, int O, int Kb)
{
    extern __shared__ char smem[];
    const uint32_t sm = smem_u32(smem);
    const int tid  = threadIdx.x;
    const int wid  = tid >> 5;
    const int lane = tid & 31;
    const int m0 = blockIdx.y * TM;
    const int n0 = blockIdx.x * TN;
    const int KCH = Kb / TKB;            // 32

    const int warp_m = (wid & 3) * 32;
    const int warp_n = (wid >> 2) * 64;

    // ldmatrix source offsets (stage-relative)
    const int mat = lane >> 3, rin = lane & 7;
    uint32_t relA[2][2], relB[4][2];
#pragma unroll
    for (int mf = 0; mf < 2; mf++) {
        int r = warp_m + mf * 16 + (mat & 1) * 8 + rin;
#pragma unroll
        for (int ks = 0; ks < 2; ks++)
            relA[mf][ks] = SMEM_CTRL + swz(r, 2 * ks + (mat >> 1));
    }
#pragma unroll
    for (int g = 0; g < 4; g++) {
        int r = warp_n + g * 16 + (mat >> 1) * 8 + rin;
#pragma unroll
        for (int ks = 0; ks < 2; ks++)
            relB[g][ks] = SMEM_CTRL + A_BLK + swz(r, 2 * ks + (mat & 1));
    }

    if (tid == 0) {
#pragma unroll
        for (int s = 0; s < STAGES; s++) {
            MBARRIER_INIT(sm + OFF_FULL  + s * 8, 1);
            MBARRIER_INIT(sm + OFF_EMPTY + s * 8, TPB);
        }
    }
    __syncthreads();

    const int8_t* Ablk = A + (size_t)blockIdx.y * KCH * A_BLK;
    const int8_t* Bblk = B + (size_t)blockIdx.x * KCH * B_BLK;

    // prologue: issue all STAGES loads
    if (tid == 0) {
#pragma unroll
        for (int s = 0; s < STAGES; s++) {
            uint32_t mb = sm + OFF_FULL + s * 8;
            MBARRIER_EXPECT_TX(mb, STAGE_BYTES);
            uint32_t sb = sm + SMEM_CTRL + s * STAGE_BYTES;
            bulk_cp(sb,         Ablk + (size_t)s * A_BLK, A_BLK, mb);
            bulk_cp(sb + A_BLK, Bblk + (size_t)s * B_BLK, B_BLK, mb);
        }
    }

    int acc[2][8][4];
#pragma unroll
    for (int a = 0; a < 2; a++)
#pragma unroll
        for (int b = 0; b < 8; b++)
#pragma unroll
            for (int c = 0; c < 4; c++) acc[a][b][c] = 0;

    for (int it = 0; it < KCH; it++) {
        const int s = it % STAGES;
        const uint32_t sbase = sm + s * STAGE_BYTES;
        MBARRIER_WAIT_PARITY(sm + OFF_FULL + s * 8, (it / STAGES) & 1);

#pragma unroll
        for (int ks = 0; ks < 2; ks++) {
            uint32_t a[2][4], b[4][4];
#pragma unroll
            for (int mf = 0; mf < 2; mf++)
                ldm_x4(a[mf][0], a[mf][1], a[mf][2], a[mf][3],
                       sbase + relA[mf][ks]);
#pragma unroll
            for (int g = 0; g < 4; g++)
                ldm_x4(b[g][0], b[g][1], b[g][2], b[g][3],
                       sbase + relB[g][ks]);
#pragma unroll
            for (int mf = 0; mf < 2; mf++)
#pragma unroll
                for (int nf = 0; nf < 8; nf++)
                    imma(acc[mf][nf], a[mf], &b[nf >> 1][(nf & 1) * 2]);
        }
        MBARRIER_ARRIVE(sm + OFF_EMPTY + s * 8);

        const int ld = it + STAGES;
        if (tid == 0 && ld < KCH) {
            const int s2 = ld % STAGES;      // == s
            MBARRIER_WAIT_PARITY(sm + OFF_EMPTY + s2 * 8, (it / STAGES) & 1);
            uint32_t mb = sm + OFF_FULL + s2 * 8;
            MBARRIER_EXPECT_TX(mb, STAGE_BYTES);
            uint32_t sb = sm + SMEM_CTRL + s2 * STAGE_BYTES;
            bulk_cp(sb,         Ablk + (size_t)ld * A_BLK, A_BLK, mb);
            bulk_cp(sb + A_BLK, Bblk + (size_t)ld * B_BLK, B_BLK, mb);
        }
    }

    // epilogue: s32 -> fp32 + bias, float2 stores
    const int rbase = m0 + warp_m + (lane >> 2);
    const int cbase = n0 + warp_n + (lane & 3) * 2;
#pragma unroll
    for (int nf = 0; nf < 8; nf++) {
        const int col = cbase + nf * 8;
        const float2 bv = *(const float2*)&bias[col];
#pragma unroll
        for (int mf = 0; mf < 2; mf++) {
            const int r0 = rbase + mf * 16;
            float2 v0, v1;
            v0.x = (float)acc[mf][nf][0] + bv.x;
            v0.y = (float)acc[mf][nf][1] + bv.y;
            v1.x = (float)acc[mf][nf][2] + bv.x;
            v1.y = (float)acc[mf][nf][3] + bv.y;
            *(float2*)&out[(size_t)r0 * O + col] = v0;
            *(float2*)&out[(size_t)(r0 + 8) * O + col] = v1;
        }
    }
}

// ---------------------------------------------------------------------------
// Launch
// ---------------------------------------------------------------------------
extern "C" void kernel_launch(void* const* d_in, const int* in_sizes, int n_in,
                              void* d_out, int out_size)
{
    const float* x = (const float*)d_in[0];
    const float* W = (const float*)d_in[1];
    const float* b = (const float*)d_in[2];
    float* out = (float*)d_out;

    const int O = in_sizes[2];            // out_features
    const int I = in_sizes[1] / O;        // in_features (K)
    const int T = in_sizes[0] / I;        // batch rows

    int8_t *Xa, *Wb;
    cudaGetSymbolAddress((void**)&Xa, g_Xa);
    cudaGetSymbolAddress((void**)&Wb, g_Wb);

    cudaFuncSetAttribute(bgemm_imma,
                         cudaFuncAttributeMaxDynamicSharedMemorySize, SMEM_TOTAL);

    const int KW16 = I / 16, KCH = I / 64;
    pack_s8_tiled<TM><<<2048, 256>>>(x, Xa, (T * I) / 16, KW16, KCH);
    pack_s8_tiled<TN><<<512,  256>>>(W, Wb, (O * I) / 16, KW16, KCH);

    dim3 grid(O / TN, T / TM);
    bgemm_imma<<<grid, TPB, SMEM_TOTAL>>>(Xa, Wb, b, out, T, O, I);
}

// round 8
// speedup vs baseline: 1.0226x; 1.0226x over previous
#include <cuda_runtime.h>
#include <cstdint>

// ============================================================================
// BLinear: out[t][o] = sum_i sign(x[t,i])*sign(W[o,i]) + b[o]
// sm_100 (no tcgen05). s8 +-1 encode -> mma.sync m16n8k32 s32 IMMA GEMM ->
// float + bias. Integer accumulation is exact (rel_err 0).
// GEMM identical to the validated round-4 kernel; pack kernels fused into one
// launch (x and W packed concurrently by disjoint block ranges).
// ============================================================================

#define TPB 256
#define TM 128
#define TN 128
#define TKB 64                    // K bytes per stage
#define STAGES 5

#define A_BYTES (TM * TKB)        // 8192
#define STAGE_BYTES (2 * A_BYTES) // 16384 (A then B)
#define SMEM_TOTAL (STAGES * STAGE_BYTES)   // 81920

// Scratch (allocation rules: __device__ globals)
__device__ __align__(256) int8_t g_Xa[8192u * 2048u];   // 16 MB packed x
__device__ __align__(256) int8_t g_Wb[2048u * 2048u];   //  4 MB packed W

__device__ __forceinline__ uint32_t smem_u32(const void* p) {
    uint32_t a;
    asm("{ .reg .u64 t; cvta.to.shared.u64 t, %1; cvt.u32.u64 %0, t; }"
        : "=r"(a) : "l"(p));
    return a;
}
__device__ __forceinline__ void cp16(uint32_t dst, const void* src) {
    asm volatile("cp.async.cg.shared.global [%0], [%1], 16;"
        :: "r"(dst), "l"(src) : "memory");
}
#define CP_COMMIT() asm volatile("cp.async.commit_group;" ::: "memory")
#define CP_WAIT(n)  asm volatile("cp.async.wait_group %0;" :: "n"(n) : "memory")

__device__ __forceinline__ void ldm_x4(uint32_t& r0, uint32_t& r1,
                                       uint32_t& r2, uint32_t& r3, uint32_t addr) {
    asm volatile("ldmatrix.sync.aligned.m8n8.x4.shared.b16 {%0,%1,%2,%3}, [%4];"
        : "=r"(r0), "=r"(r1), "=r"(r2), "=r"(r3) : "r"(addr));
}
__device__ __forceinline__ void imma(int* d, const uint32_t* a, const uint32_t* b) {
    asm volatile("mma.sync.aligned.m16n8k32.row.col.s32.s8.s8.s32 "
        "{%0,%1,%2,%3}, {%4,%5,%6,%7}, {%8,%9}, {%0,%1,%2,%3};"
        : "+r"(d[0]), "+r"(d[1]), "+r"(d[2]), "+r"(d[3])
        : "r"(a[0]), "r"(a[1]), "r"(a[2]), "r"(a[3]), "r"(b[0]), "r"(b[1]));
}

// 16B-chunk XOR swizzle within a 64B k-row: conflict-free for cp.async stores
// and for ldmatrix 8-row read phases.
__device__ __forceinline__ uint32_t swz(int r, int c) {
    return (uint32_t)(r * TKB + ((c ^ ((r >> 1) & 3)) << 4));
}

// ---------------------------------------------------------------------------
// Fused pack: fp32 -> s8 sign (+1 -> 0x01, -1 -> 0xFF); 16 bytes out per iter.
// Blocks [0, PACK_XB) pack x; blocks [PACK_XB, PACK_XB+PACK_WB) pack W.
// ---------------------------------------------------------------------------
#define PACK_XB 2048
#define PACK_WB 512
__global__ void __launch_bounds__(256)
pack_fused(const float* __restrict__ x, int8_t* __restrict__ xa,
           const float* __restrict__ W, int8_t* __restrict__ wb,
           int nx16, int nw16)
{
    const bool isX = blockIdx.x < PACK_XB;
    const float* src = isX ? x : W;
    int8_t* dst      = isX ? xa : wb;
    const int n16    = isX ? nx16 : nw16;
    const int nblk   = isX ? PACK_XB : PACK_WB;
    const int bid    = isX ? blockIdx.x : blockIdx.x - PACK_XB;

    int idx = bid * 256 + threadIdx.x;
    int stride = nblk * 256;
    const float4* s4 = (const float4*)src;
    uint4* d4 = (uint4*)dst;
    for (int i = idx; i < n16; i += stride) {
        uint32_t w[4];
#pragma unroll
        for (int k = 0; k < 4; k++) {
            float4 f = s4[(size_t)i * 4 + k];
            uint32_t sb = (__float_as_uint(f.x) >> 31)
                        | ((__float_as_uint(f.y) >> 31) << 8)
                        | ((__float_as_uint(f.z) >> 31) << 16)
                        | ((__float_as_uint(f.w) >> 31) << 24);
            w[k] = 0x01010101u ^ (sb * 0xFEu);   // per byte: 0x01 or 0xFF
        }
        d4[i] = make_uint4(w[0], w[1], w[2], w[3]);
    }
}

// ---------------------------------------------------------------------------
// IMMA GEMM: out[T,O] = A[T,K]s8 @ B[O,K]s8^T (as s32) + bias, fp32 out.
// Block 128x128, 8 warps of 64x32, 5-stage cp.async pipeline.
// (Identical to the validated round-4 kernel.)
// ---------------------------------------------------------------------------
__global__ void __launch_bounds__(TPB, 2)
bgemm_imma(const int8_t* __restrict__ A, const int8_t* __restrict__ B,
           const float* __restrict__ bias, float* __restrict__ out,
           int T, int O, int Kb)
{
    extern __shared__ char smem[];
    const uint32_t sm = smem_u32(smem);
    const int tid  = threadIdx.x;
    const int wid  = tid >> 5;
    const int lane = tid & 31;
    const int m0 = blockIdx.y * TM;
    const int n0 = blockIdx.x * TN;
    const int KCH = Kb / TKB;

    const int warp_m = (wid & 1) * 64;    // 2 m-groups
    const int warp_n = (wid >> 1) * 32;   // 4 n-groups

    // per-lane ldmatrix source offsets (stage-relative), both ksteps
    const int mat = lane >> 3, rin = lane & 7;
    uint32_t relA[4][2], relB[2][2];
#pragma unroll
    for (int mf = 0; mf < 4; mf++) {
        int r = warp_m + mf * 16 + (mat & 1) * 8 + rin;
        int cpar = mat >> 1;
#pragma unroll
        for (int ks = 0; ks < 2; ks++)
            relA[mf][ks] = swz(r, 2 * ks + cpar);
    }
#pragma unroll
    for (int g = 0; g < 2; g++) {
        int r = warp_n + g * 16 + (mat >> 1) * 8 + rin;
        int cpar = mat & 1;
#pragma unroll
        for (int ks = 0; ks < 2; ks++)
            relB[g][ks] = (uint32_t)A_BYTES + swz(r, 2 * ks + cpar);
    }

    const int8_t* gA = A + (size_t)m0 * Kb;
    const int8_t* gB = B + (size_t)n0 * Kb;

    // cp.async task split: i<512 -> A (r=i>>2,c=i&3), else B
    const int i0 = tid;                    // + k*TPB, k=0..3
    auto load_stage = [&](int slot, int ch) {
        uint32_t sbase = sm + slot * STAGE_BYTES;
        size_t koff = (size_t)ch * TKB;
#pragma unroll
        for (int k = 0; k < 4; k++) {
            int i = i0 + k * TPB;
            if (i < 512) {
                int r = i >> 2, c = i & 3;
                cp16(sbase + swz(r, c), gA + (size_t)r * Kb + koff + c * 16);
            } else {
                int j = i - 512;
                int r = j >> 2, c = j & 3;
                cp16(sbase + A_BYTES + swz(r, c),
                     gB + (size_t)r * Kb + koff + c * 16);
            }
        }
    };

    int acc[4][4][4];
#pragma unroll
    for (int a = 0; a < 4; a++)
#pragma unroll
        for (int b = 0; b < 4; b++)
#pragma unroll
            for (int c = 0; c < 4; c++) acc[a][b][c] = 0;

    // prologue: fill stages 0..3
#pragma unroll
    for (int s = 0; s < STAGES - 1; s++) {
        load_stage(s, s);
        CP_COMMIT();
    }

    for (int it = 0; it < KCH; it++) {
        const int slot = it % STAGES;
        CP_WAIT(STAGES - 2);
        __syncthreads();

        const uint32_t sbase = sm + slot * STAGE_BYTES;
#pragma unroll
        for (int ks = 0; ks < 2; ks++) {
            uint32_t a[4][4], b[2][4];
#pragma unroll
            for (int mf = 0; mf < 4; mf++)
                ldm_x4(a[mf][0], a[mf][1], a[mf][2], a[mf][3],
                       sbase + relA[mf][ks]);
#pragma unroll
            for (int g = 0; g < 2; g++)
                ldm_x4(b[g][0], b[g][1], b[g][2], b[g][3],
                       sbase + relB[g][ks]);
#pragma unroll
            for (int mf = 0; mf < 4; mf++)
#pragma unroll
                for (int nf = 0; nf < 4; nf++)
                    imma(acc[mf][nf], a[mf], &b[nf >> 1][(nf & 1) * 2]);
        }

        const int ld = it + STAGES - 1;
        if (ld < KCH) load_stage(ld % STAGES, ld);
        CP_COMMIT();
    }

    // epilogue: s32 -> fp32 + bias, float2 stores (32B per quad, coalesced)
    const int rbase = m0 + warp_m + (lane >> 2);
    const int cbase = n0 + warp_n + (lane & 3) * 2;
#pragma unroll
    for (int nf = 0; nf < 4; nf++) {
        const int col = cbase + nf * 8;
        const float2 bv = *(const float2*)&bias[col];
#pragma unroll
        for (int mf = 0; mf < 4; mf++) {
            const int r0 = rbase + mf * 16;
            float2 v0, v1;
            v0.x = (float)acc[mf][nf][0] + bv.x;
            v0.y = (float)acc[mf][nf][1] + bv.y;
            v1.x = (float)acc[mf][nf][2] + bv.x;
            v1.y = (float)acc[mf][nf][3] + bv.y;
            *(float2*)&out[(size_t)r0 * O + col] = v0;
            *(float2*)&out[(size_t)(r0 + 8) * O + col] = v1;
        }
    }
}

// ---------------------------------------------------------------------------
// Launch
// ---------------------------------------------------------------------------
extern "C" void kernel_launch(void* const* d_in, const int* in_sizes, int n_in,
                              void* d_out, int out_size)
{
    const float* x = (const float*)d_in[0];
    const float* W = (const float*)d_in[1];
    const float* b = (const float*)d_in[2];
    float* out = (float*)d_out;

    const int O = in_sizes[2];            // out_features
    const int I = in_sizes[1] / O;        // in_features (K)
    const int T = in_sizes[0] / I;        // batch rows

    int8_t *Xa, *Wb;
    cudaGetSymbolAddress((void**)&Xa, g_Xa);
    cudaGetSymbolAddress((void**)&Wb, g_Wb);

    cudaFuncSetAttribute(bgemm_imma,
                         cudaFuncAttributeMaxDynamicSharedMemorySize, SMEM_TOTAL);

    pack_fused<<<PACK_XB + PACK_WB, 256>>>(x, Xa, W, Wb,
                                           (T * I) / 16, (O * I) / 16);

    dim3 grid(O / TN, T / TM);
    bgemm_imma<<<grid, TPB, SMEM_TOTAL>>>(Xa, Wb, b, out, T, O, I);
}